// round 3
// baseline (speedup 1.0000x reference)
#include <cuda_runtime.h>
#include <cstdint>

#define NN 50000
#define NE 640000
#define IND 128
#define OUTD 128
#define NH 4
#define HD 32

// -------- scratch (static device globals; 16B-aligned) --------
__device__ __align__(16) float g_Wh[(size_t)NN * OUTD];    // 25.6 MB
__device__ __align__(16) float g_agg[(size_t)NN * OUTD];   // 25.6 MB
__device__ __align__(16) float g_attn[(size_t)NE * NH];    // 10.2 MB
__device__ __align__(16) float g_s1[NN * NH];
__device__ __align__(16) float g_s2[NN * NH];
__device__ __align__(16) float g_maxv[NN * NH];
__device__ __align__(16) float g_den[NN * NH];
__device__ __align__(16) int   g_src[NE];
__device__ __align__(16) int   g_dst[NE];
__device__ int g_is64;

// -------- detect edge_index width: int64 → all high words zero --------
__global__ void k_detect(const void* __restrict__ ei) {
    if (threadIdx.x == 0 && blockIdx.x == 0) {
        const uint2* p = (const uint2*)ei;
        int is64 = 1;
        for (int i = 0; i < 1024; i++) {
            if (p[i].y != 0u) { is64 = 0; break; }
        }
        g_is64 = is64;
    }
}

// -------- decode edge_index into clamped int32 src/dst --------
__global__ void k_decode(const void* __restrict__ ei) {
    int i = blockIdx.x * blockDim.x + threadIdx.x;
    if (i >= 2 * NE) return;
    long long v;
    if (g_is64) v = ((const long long*)ei)[i];
    else        v = (long long)((const int*)ei)[i];
    int iv = (int)v;
    iv = iv < 0 ? 0 : (iv >= NN ? NN - 1 : iv);
    if (i < NE) g_src[i] = iv;
    else        g_dst[i - NE] = iv;
}

// -------- init: zero agg/den, maxv = -1e9 --------
__global__ void k_init() {
    int i = blockIdx.x * blockDim.x + threadIdx.x;
    int stride = gridDim.x * blockDim.x;
    float4 z = make_float4(0.f, 0.f, 0.f, 0.f);
    float4 m = make_float4(-1e9f, -1e9f, -1e9f, -1e9f);
    float4* agg4 = (float4*)g_agg;
    float4* den4 = (float4*)g_den;
    float4* max4 = (float4*)g_maxv;
    for (int t = i; t < NN * 32; t += stride) agg4[t] = z;
    for (int t = i; t < NN; t += stride) { den4[t] = z; max4[t] = m; }
}

// -------- GEMM: Wh = h @ W^T --------
__global__ void k_gemm(const float* __restrict__ h, const float* __restrict__ W) {
    __shared__ float Ws[32][128];
    __shared__ float Hs[64][32];

    int t = threadIdx.x;
    int tx = t & 31;
    int ty = t >> 5;
    int rbase = blockIdx.x * 64;

    float acc[8][4];
#pragma unroll
    for (int i = 0; i < 8; i++)
#pragma unroll
        for (int j = 0; j < 4; j++) acc[i][j] = 0.f;

    for (int kc = 0; kc < 128; kc += 32) {
        __syncthreads();
        {
            int c = t >> 1;
            int k0 = (t & 1) * 16;
#pragma unroll
            for (int j = 0; j < 4; j++) {
                float4 w = *(const float4*)(W + c * 128 + kc + k0 + j * 4);
                Ws[k0 + j * 4 + 0][c] = w.x;
                Ws[k0 + j * 4 + 1][c] = w.y;
                Ws[k0 + j * 4 + 2][c] = w.z;
                Ws[k0 + j * 4 + 3][c] = w.w;
            }
        }
        {
            int r = t >> 2;
            int k0 = (t & 3) * 8;
            int row = rbase + r;
            float4 a0 = make_float4(0.f, 0.f, 0.f, 0.f), a1 = a0;
            if (row < NN) {
                a0 = *(const float4*)(h + (size_t)row * 128 + kc + k0);
                a1 = *(const float4*)(h + (size_t)row * 128 + kc + k0 + 4);
            }
            *(float4*)&Hs[r][k0] = a0;
            *(float4*)&Hs[r][k0 + 4] = a1;
        }
        __syncthreads();

#pragma unroll 8
        for (int k = 0; k < 32; k++) {
            float4 w = *(const float4*)&Ws[k][tx * 4];
#pragma unroll
            for (int i = 0; i < 8; i++) {
                float hv = Hs[ty * 8 + i][k];
                acc[i][0] += hv * w.x;
                acc[i][1] += hv * w.y;
                acc[i][2] += hv * w.z;
                acc[i][3] += hv * w.w;
            }
        }
    }

#pragma unroll
    for (int i = 0; i < 8; i++) {
        int row = rbase + ty * 8 + i;
        if (row < NN) {
            *(float4*)(g_Wh + (size_t)row * 128 + tx * 4) =
                make_float4(acc[i][0], acc[i][1], acc[i][2], acc[i][3]);
        }
    }
}

// -------- per-node attention dots --------
__global__ void k_sdots(const float* __restrict__ a) {
    int gw = (blockIdx.x * blockDim.x + threadIdx.x) >> 5;
    if (gw >= NN) return;
    int lane = threadIdx.x & 31;
    int head = lane >> 3;
    int dd = (lane & 7) * 4;
    float4 w = *(const float4*)(g_Wh + (size_t)gw * 128 + lane * 4);
    float4 a1 = *(const float4*)(a + head * 64 + dd);
    float4 a2 = *(const float4*)(a + head * 64 + 32 + dd);
    float p1 = w.x * a1.x + w.y * a1.y + w.z * a1.z + w.w * a1.w;
    float p2 = w.x * a2.x + w.y * a2.y + w.z * a2.z + w.w * a2.w;
#pragma unroll
    for (int o = 1; o < 8; o <<= 1) {
        p1 += __shfl_xor_sync(0xffffffffu, p1, o);
        p2 += __shfl_xor_sync(0xffffffffu, p2, o);
    }
    if ((lane & 7) == 0) {
        g_s1[gw * 4 + head] = p1;
        g_s2[gw * 4 + head] = p2;
    }
}

__device__ __forceinline__ void atomicMaxFloat(float* addr, float v) {
    if (v >= 0.f)
        atomicMax((int*)addr, __float_as_int(v));
    else
        atomicMin((unsigned int*)addr, __float_as_uint(v));
}

// -------- edge pass A: logits + segment max --------
__global__ void k_edgeA(const float* __restrict__ ef,
                        const float* __restrict__ We) {
    __shared__ float sWe[64];
    if (threadIdx.x < 64) sWe[threadIdx.x] = We[threadIdx.x];
    __syncthreads();

    int e = blockIdx.x * blockDim.x + threadIdx.x;
    if (e >= NE) return;
    int s = g_src[e];
    int d = g_dst[e];

    float s1v[4], s2v[4];
    *(float4*)s1v = *(const float4*)(g_s1 + s * 4);
    *(float4*)s2v = *(const float4*)(g_s2 + d * 4);

    float efv[16];
#pragma unroll
    for (int j = 0; j < 4; j++)
        *(float4*)(efv + j * 4) = *(const float4*)(ef + (size_t)e * 16 + j * 4);

    float att[4];
#pragma unroll
    for (int hh = 0; hh < 4; hh++) {
        float tv = s1v[hh] + s2v[hh];
        tv = tv > 0.f ? tv : 0.2f * tv;
        float wsum = 0.f;
#pragma unroll
        for (int j = 0; j < 16; j++) wsum += efv[j] * sWe[hh * 16 + j];
        att[hh] = tv + wsum;
    }
    *(float4*)(g_attn + (size_t)e * 4) = *(float4*)att;
#pragma unroll
    for (int hh = 0; hh < 4; hh++) atomicMaxFloat(&g_maxv[d * 4 + hh], att[hh]);
}

// -------- edge pass B: exp, denom, unnormalized scatter-add (one warp/edge) --------
__global__ void k_edgeB() {
    int e = (int)((blockIdx.x * (unsigned)blockDim.x + threadIdx.x) >> 5);
    if (e >= NE) return;
    int lane = threadIdx.x & 31;

    int s = g_src[e];
    int d = g_dst[e];

    float p = 0.f;
    if (lane < 4) {
        float att = g_attn[(size_t)e * 4 + lane];
        float mv = g_maxv[d * 4 + lane];
        p = expf(att - mv);
        atomicAdd(&g_den[d * 4 + lane], p);
    }
    float ph = __shfl_sync(0xffffffffu, p, lane >> 3);

    float4 w = *(const float4*)(g_Wh + (size_t)s * 128 + lane * 4);
    float* dst = g_agg + (size_t)d * 128 + lane * 4;
    atomicAdd(dst + 0, w.x * ph);
    atomicAdd(dst + 1, w.y * ph);
    atomicAdd(dst + 2, w.z * ph);
    atomicAdd(dst + 3, w.w * ph);
}

// -------- node pass C: normalize, gelu (exact), layernorm (one warp/node) --------
__global__ void k_node(const float* __restrict__ scale,
                       const float* __restrict__ bias,
                       float* __restrict__ out) {
    int n = (int)((blockIdx.x * (unsigned)blockDim.x + threadIdx.x) >> 5);
    if (n >= NN) return;
    int lane = threadIdx.x & 31;
    int head = lane >> 3;

    float den = g_den[n * 4 + head] + 1e-9f;
    float inv = 1.f / den;
    float4 v = *(const float4*)(g_agg + (size_t)n * 128 + lane * 4);
    float x[4] = {v.x * inv, v.y * inv, v.z * inv, v.w * inv};

#pragma unroll
    for (int j = 0; j < 4; j++) {
        float xx = x[j];
        x[j] = 0.5f * xx * (1.f + erff(xx * 0.70710678118654752f));
    }

    float sum = x[0] + x[1] + x[2] + x[3];
    float sq = x[0] * x[0] + x[1] * x[1] + x[2] * x[2] + x[3] * x[3];
#pragma unroll
    for (int o = 16; o > 0; o >>= 1) {
        sum += __shfl_xor_sync(0xffffffffu, sum, o);
        sq += __shfl_xor_sync(0xffffffffu, sq, o);
    }
    float mu = sum * (1.f / 128.f);
    float var = sq * (1.f / 128.f) - mu * mu;
    float rstd = rsqrtf(var + 1e-5f);

    float4 sc = *(const float4*)(scale + lane * 4);
    float4 bi = *(const float4*)(bias + lane * 4);
    float4 o4;
    o4.x = (x[0] - mu) * rstd * sc.x + bi.x;
    o4.y = (x[1] - mu) * rstd * sc.y + bi.y;
    o4.z = (x[2] - mu) * rstd * sc.z + bi.z;
    o4.w = (x[3] - mu) * rstd * sc.w + bi.w;
    *(float4*)(out + (size_t)n * 128 + lane * 4) = o4;
}

extern "C" void kernel_launch(void* const* d_in, const int* in_sizes, int n_in,
                              void* d_out, int out_size) {
    // remap inputs by element count (robust to ordering)
    int ih = 0, iei = 1, ief = 2, iW = 3, iWe = 4, ia = 5, isc = 6, ibi = 7;
    {
        int fh = -1, fei = -1, fef = -1, fW = -1, fWe = -1, fa = -1, fsc = -1, fbi = -1;
        for (int i = 0; i < n_in; i++) {
            int s = in_sizes[i];
            if (s == NN * IND) fh = i;
            else if (s == 2 * NE) fei = i;
            else if (s == NE * 16) fef = i;
            else if (s == OUTD * IND) fW = i;
            else if (s == NH * 16) fWe = i;
            else if (s == NH * 2 * HD) fa = i;
            else if (s == OUTD) { if (fsc < 0) fsc = i; else fbi = i; }
        }
        if (fh >= 0 && fei >= 0 && fef >= 0 && fW >= 0 && fWe >= 0 && fa >= 0 &&
            fsc >= 0 && fbi >= 0) {
            ih = fh; iei = fei; ief = fef; iW = fW; iWe = fWe; ia = fa;
            isc = fsc; ibi = fbi;
        }
    }
    const float* h = (const float*)d_in[ih];
    const void* ei = d_in[iei];
    const float* ef = (const float*)d_in[ief];
    const float* W = (const float*)d_in[iW];
    const float* We = (const float*)d_in[iWe];
    const float* a = (const float*)d_in[ia];
    const float* sc = (const float*)d_in[isc];
    const float* bi = (const float*)d_in[ibi];
    float* out = (float*)d_out;

    k_detect<<<1, 32>>>(ei);
    k_decode<<<(2 * NE + 255) / 256, 256>>>(ei);
    k_init<<<2048, 256>>>();
    k_gemm<<<(NN + 63) / 64, 256>>>(h, W);
    k_sdots<<<(NN * 32 + 255) / 256, 256>>>(a);
    k_edgeA<<<(NE + 255) / 256, 256>>>(ef, We);
    k_edgeB<<<(int)(((size_t)NE * 32 + 255) / 256), 256>>>();
    k_node<<<(NN * 32 + 255) / 256, 256>>>(sc, bi, out);
}

// round 4
// speedup vs baseline: 1.3171x; 1.3171x over previous
#include <cuda_runtime.h>
#include <cstdint>

#define NN 50000
#define NE 640000
#define IND 128
#define OUTD 128
#define NH 4
#define HD 32

// -------- scratch --------
__device__ __align__(16) float g_Wh[(size_t)NN * OUTD];    // 25.6 MB
__device__ __align__(16) float g_agg[(size_t)NN * OUTD];   // 25.6 MB
__device__ __align__(16) float g_s1[NN * NH];
__device__ __align__(16) float g_s2[NN * NH];
__device__ __align__(16) float g_den[NN * NH];
__device__ __align__(16) int   g_src[NE];
__device__ __align__(16) int   g_dst[NE];
__device__ int g_is64;

// -------- detect edge_index width: int64 → high words all zero --------
__global__ void k_detect(const void* __restrict__ ei) {
    if (threadIdx.x == 0 && blockIdx.x == 0) {
        const uint2* p = (const uint2*)ei;
        int is64 = 1;
        for (int i = 0; i < 1024; i++) {
            if (p[i].y != 0u) { is64 = 0; break; }
        }
        g_is64 = is64;
    }
}

// -------- decode edge_index into clamped int32 src/dst --------
__global__ void k_decode(const void* __restrict__ ei) {
    int i = blockIdx.x * blockDim.x + threadIdx.x;
    if (i >= 2 * NE) return;
    long long v;
    if (g_is64) v = ((const long long*)ei)[i];
    else        v = (long long)((const int*)ei)[i];
    int iv = (int)v;
    iv = iv < 0 ? 0 : (iv >= NN ? NN - 1 : iv);
    if (i < NE) g_src[i] = iv;
    else        g_dst[i - NE] = iv;
}

// -------- init: zero agg/den --------
__global__ void k_init() {
    int i = blockIdx.x * blockDim.x + threadIdx.x;
    int stride = gridDim.x * blockDim.x;
    float4 z = make_float4(0.f, 0.f, 0.f, 0.f);
    float4* agg4 = (float4*)g_agg;
    float4* den4 = (float4*)g_den;
    for (int t = i; t < NN * 32; t += stride) agg4[t] = z;
    for (int t = i; t < NN; t += stride) den4[t] = z;
}

// -------- GEMM: Wh = h @ W^T, fused s1/s2 attention dots --------
// block = 256 threads, 64 rows x 128 cols, 8x4 register tile/thread
__global__ void k_gemm(const float* __restrict__ h, const float* __restrict__ W,
                       const float* __restrict__ a) {
    __shared__ float Ws[32][128];
    __shared__ float Hs[64][32];

    int t = threadIdx.x;
    int tx = t & 31;
    int ty = t >> 5;
    int rbase = blockIdx.x * 64;

    float acc[8][4];
#pragma unroll
    for (int i = 0; i < 8; i++)
#pragma unroll
        for (int j = 0; j < 4; j++) acc[i][j] = 0.f;

    for (int kc = 0; kc < 128; kc += 32) {
        __syncthreads();
        {
            int c = t >> 1;
            int k0 = (t & 1) * 16;
#pragma unroll
            for (int j = 0; j < 4; j++) {
                float4 w = *(const float4*)(W + c * 128 + kc + k0 + j * 4);
                Ws[k0 + j * 4 + 0][c] = w.x;
                Ws[k0 + j * 4 + 1][c] = w.y;
                Ws[k0 + j * 4 + 2][c] = w.z;
                Ws[k0 + j * 4 + 3][c] = w.w;
            }
        }
        {
            int r = t >> 2;
            int k0 = (t & 3) * 8;
            int row = rbase + r;
            float4 a0 = make_float4(0.f, 0.f, 0.f, 0.f), a1 = a0;
            if (row < NN) {
                a0 = *(const float4*)(h + (size_t)row * 128 + kc + k0);
                a1 = *(const float4*)(h + (size_t)row * 128 + kc + k0 + 4);
            }
            *(float4*)&Hs[r][k0] = a0;
            *(float4*)&Hs[r][k0 + 4] = a1;
        }
        __syncthreads();

#pragma unroll
        for (int k = 0; k < 32; k += 4) {
            float4 w0 = *(const float4*)&Ws[k + 0][tx * 4];
            float4 w1 = *(const float4*)&Ws[k + 1][tx * 4];
            float4 w2 = *(const float4*)&Ws[k + 2][tx * 4];
            float4 w3 = *(const float4*)&Ws[k + 3][tx * 4];
#pragma unroll
            for (int i = 0; i < 8; i++) {
                float4 hv = *(const float4*)&Hs[ty * 8 + i][k];
                acc[i][0] += hv.x * w0.x; acc[i][1] += hv.x * w0.y;
                acc[i][2] += hv.x * w0.z; acc[i][3] += hv.x * w0.w;
                acc[i][0] += hv.y * w1.x; acc[i][1] += hv.y * w1.y;
                acc[i][2] += hv.y * w1.z; acc[i][3] += hv.y * w1.w;
                acc[i][0] += hv.z * w2.x; acc[i][1] += hv.z * w2.y;
                acc[i][2] += hv.z * w2.z; acc[i][3] += hv.z * w2.w;
                acc[i][0] += hv.w * w3.x; acc[i][1] += hv.w * w3.y;
                acc[i][2] += hv.w * w3.z; acc[i][3] += hv.w * w3.w;
            }
        }
    }

    // attention vector slices for this lane's 4 columns
    int head = tx >> 3;
    int dd = (tx & 7) * 4;
    float4 av1 = *(const float4*)(a + head * 64 + dd);
    float4 av2 = *(const float4*)(a + head * 64 + 32 + dd);

#pragma unroll
    for (int i = 0; i < 8; i++) {
        int row = rbase + ty * 8 + i;
        bool ok = row < NN;
        if (ok) {
            *(float4*)(g_Wh + (size_t)row * 128 + tx * 4) =
                make_float4(acc[i][0], acc[i][1], acc[i][2], acc[i][3]);
        }
        // fused s1/s2: reduce within each 8-lane head group
        float p1 = acc[i][0] * av1.x + acc[i][1] * av1.y + acc[i][2] * av1.z + acc[i][3] * av1.w;
        float p2 = acc[i][0] * av2.x + acc[i][1] * av2.y + acc[i][2] * av2.z + acc[i][3] * av2.w;
#pragma unroll
        for (int o = 1; o < 8; o <<= 1) {
            p1 += __shfl_xor_sync(0xffffffffu, p1, o);
            p2 += __shfl_xor_sync(0xffffffffu, p2, o);
        }
        if (ok && (tx & 7) == 0) {
            g_s1[row * 4 + head] = p1;
            g_s2[row * 4 + head] = p2;
        }
    }
}

// -------- fused edge pass: logits, exp (no max shift), denom, v4-RED scatter --------
// one warp per edge, 8 edges per 256-thread block
__global__ void k_edge(const float* __restrict__ ef) {
    extern __shared__ float sWe[];  // 64 floats staged by kernel_launch copy kernel below
    // (sWe filled via param-less trick: we stage from global g_We copy)
    int e = (int)((blockIdx.x * (unsigned)blockDim.x + threadIdx.x) >> 5);
    int lane = threadIdx.x & 31;
    if (e >= NE) return;

    int s = g_src[e];
    int d = g_dst[e];

    float p = 0.f;
    if (lane < 4) {
        float s1 = g_s1[s * 4 + lane];
        float s2 = g_s2[d * 4 + lane];
        float tv = s1 + s2;
        tv = tv > 0.f ? tv : 0.2f * tv;
        float wsum = 0.f;
#pragma unroll
        for (int j = 0; j < 4; j++) {
            float4 efv = *(const float4*)(ef + (size_t)e * 16 + j * 4);
            float4 wv = *(const float4*)(sWe + lane * 16 + j * 4);
            wsum += efv.x * wv.x + efv.y * wv.y + efv.z * wv.z + efv.w * wv.w;
        }
        p = expf(tv + wsum);
        atomicAdd(&g_den[d * 4 + lane], p);
    }
    float ph = __shfl_sync(0xffffffffu, p, lane >> 3);

    float4 w = *(const float4*)(g_Wh + (size_t)s * 128 + lane * 4);
    unsigned long long dst =
        (unsigned long long)__cvta_generic_to_global(g_agg + (size_t)d * 128 + lane * 4);
    asm volatile("red.global.add.v4.f32 [%0], {%1,%2,%3,%4};"
                 :: "l"(dst), "f"(w.x * ph), "f"(w.y * ph), "f"(w.z * ph), "f"(w.w * ph)
                 : "memory");
}

// wrapper that stages We into dynamic smem at block start
__global__ void k_edge_full(const float* __restrict__ ef, const float* __restrict__ We) {
    __shared__ float sWe[64];
    if (threadIdx.x < 64) sWe[threadIdx.x] = We[threadIdx.x];
    __syncthreads();

    int e = (int)((blockIdx.x * (unsigned)blockDim.x + threadIdx.x) >> 5);
    int lane = threadIdx.x & 31;
    if (e >= NE) return;

    int s = g_src[e];
    int d = g_dst[e];

    float p = 0.f;
    if (lane < 4) {
        float s1 = g_s1[s * 4 + lane];
        float s2 = g_s2[d * 4 + lane];
        float tv = s1 + s2;
        tv = tv > 0.f ? tv : 0.2f * tv;
        float wsum = 0.f;
#pragma unroll
        for (int j = 0; j < 4; j++) {
            float4 efv = *(const float4*)(ef + (size_t)e * 16 + j * 4);
            float4 wv = *(const float4*)(sWe + lane * 16 + j * 4);
            wsum += efv.x * wv.x + efv.y * wv.y + efv.z * wv.z + efv.w * wv.w;
        }
        p = expf(tv + wsum);
        atomicAdd(&g_den[d * 4 + lane], p);
    }
    float ph = __shfl_sync(0xffffffffu, p, lane >> 3);

    float4 w = *(const float4*)(g_Wh + (size_t)s * 128 + lane * 4);
    unsigned long long dst =
        (unsigned long long)__cvta_generic_to_global(g_agg + (size_t)d * 128 + lane * 4);
    asm volatile("red.global.add.v4.f32 [%0], {%1,%2,%3,%4};"
                 :: "l"(dst), "f"(w.x * ph), "f"(w.y * ph), "f"(w.z * ph), "f"(w.w * ph)
                 : "memory");
}

// -------- node pass: normalize, gelu (exact), layernorm (one warp/node) --------
__global__ void k_node(const float* __restrict__ scale,
                       const float* __restrict__ bias,
                       float* __restrict__ out) {
    int n = (int)((blockIdx.x * (unsigned)blockDim.x + threadIdx.x) >> 5);
    if (n >= NN) return;
    int lane = threadIdx.x & 31;
    int head = lane >> 3;

    float den = g_den[n * 4 + head] + 1e-9f;
    float inv = 1.f / den;
    float4 v = *(const float4*)(g_agg + (size_t)n * 128 + lane * 4);
    float x[4] = {v.x * inv, v.y * inv, v.z * inv, v.w * inv};

#pragma unroll
    for (int j = 0; j < 4; j++) {
        float xx = x[j];
        x[j] = 0.5f * xx * (1.f + erff(xx * 0.70710678118654752f));
    }

    float sum = x[0] + x[1] + x[2] + x[3];
    float sq = x[0] * x[0] + x[1] * x[1] + x[2] * x[2] + x[3] * x[3];
#pragma unroll
    for (int o = 16; o > 0; o >>= 1) {
        sum += __shfl_xor_sync(0xffffffffu, sum, o);
        sq += __shfl_xor_sync(0xffffffffu, sq, o);
    }
    float mu = sum * (1.f / 128.f);
    float var = sq * (1.f / 128.f) - mu * mu;
    float rstd = rsqrtf(var + 1e-5f);

    float4 sc = *(const float4*)(scale + lane * 4);
    float4 bi = *(const float4*)(bias + lane * 4);
    float4 o4;
    o4.x = (x[0] - mu) * rstd * sc.x + bi.x;
    o4.y = (x[1] - mu) * rstd * sc.y + bi.y;
    o4.z = (x[2] - mu) * rstd * sc.z + bi.z;
    o4.w = (x[3] - mu) * rstd * sc.w + bi.w;
    *(float4*)(out + (size_t)n * 128 + lane * 4) = o4;
}

extern "C" void kernel_launch(void* const* d_in, const int* in_sizes, int n_in,
                              void* d_out, int out_size) {
    // remap inputs by element count (robust to ordering)
    int ih = 0, iei = 1, ief = 2, iW = 3, iWe = 4, ia = 5, isc = 6, ibi = 7;
    {
        int fh = -1, fei = -1, fef = -1, fW = -1, fWe = -1, fa = -1, fsc = -1, fbi = -1;
        for (int i = 0; i < n_in; i++) {
            int s = in_sizes[i];
            if (s == NN * IND) fh = i;
            else if (s == 2 * NE) fei = i;
            else if (s == NE * 16) fef = i;
            else if (s == OUTD * IND) fW = i;
            else if (s == NH * 16) fWe = i;
            else if (s == NH * 2 * HD) fa = i;
            else if (s == OUTD) { if (fsc < 0) fsc = i; else fbi = i; }
        }
        if (fh >= 0 && fei >= 0 && fef >= 0 && fW >= 0 && fWe >= 0 && fa >= 0 &&
            fsc >= 0 && fbi >= 0) {
            ih = fh; iei = fei; ief = fef; iW = fW; iWe = fWe; ia = fa;
            isc = fsc; ibi = fbi;
        }
    }
    const float* h = (const float*)d_in[ih];
    const void* ei = d_in[iei];
    const float* ef = (const float*)d_in[ief];
    const float* W = (const float*)d_in[iW];
    const float* We = (const float*)d_in[iWe];
    const float* a = (const float*)d_in[ia];
    const float* sc = (const float*)d_in[isc];
    const float* bi = (const float*)d_in[ibi];
    float* out = (float*)d_out;

    k_detect<<<1, 32>>>(ei);
    k_decode<<<(2 * NE + 255) / 256, 256>>>(ei);
    k_init<<<2048, 256>>>();
    k_gemm<<<(NN + 63) / 64, 256>>>(h, W, a);
    k_edge_full<<<(NE + 7) / 8, 256>>>(ef, We);
    k_node<<<(NN * 32 + 255) / 256, 256>>>(sc, bi, out);
}